// round 11
// baseline (speedup 1.0000x reference)
#include <cuda_runtime.h>
#include <math.h>
#include <stdint.h>

#define B 32
#define S 512
#define H 256
#define T 48
#define START_IDX 46
#define STOP_IDX 47

// Scratch (no allocations allowed). g_expEm padded by 512 floats so the
// unguarded depth-4 prefetch ring may overshoot harmlessly (pad kept zero).
__device__ float g_expEm[B * S * T + 512];   // 3 MB + pad
__device__ float g_emAtTag[B * S];           // 64 KB

#define FMA2(acc, a, b) \
    asm("fma.rn.f32x2 %0, %1, %2, %0;" : "+l"(acc) : "l"(a), "l"(b))
#define ADD2(out, a, b) \
    asm("add.rn.f32x2 %0, %1, %2;" : "=l"(out) : "l"(a), "l"(b))
#define PACK2(out, lo, hi) \
    asm("mov.b64 %0, {%1, %2};" : "=l"(out) : "f"(lo), "f"(hi))
#define UNPACK2(lo, hi, in) \
    asm("mov.b64 {%0, %1}, %2;" : "=f"(lo), "=f"(hi) : "l"(in))

// ---------------------------------------------------------------------------
// Kernel A: emission = feat @ W + bias; store exp(emission) and em[b,s,tags[b,s]]
// Grid: 128 blocks x 256 threads. Each block: 128 rows x 48 cols, K=256.
// ---------------------------------------------------------------------------
__global__ __launch_bounds__(256) void emis_kernel(
    const float* __restrict__ feat,   // [B*S, H]
    const float* __restrict__ Wm,     // [H, T]
    const float* __restrict__ bias,   // [T]
    const int*   __restrict__ tags)   // [B*S]
{
    const int P = 129;                       // smem pitch (conflict break)
    __shared__ float sh_W[64 * T];           // 12 KB
    __shared__ float sh_feat[64 * P];        // 33 KB  (transposed: [k][row])

    const int tid  = threadIdx.x;
    const int row0 = blockIdx.x * 128;
    const int rg   = tid >> 3;   // 0..31 -> rows rg*4..rg*4+3
    const int cg   = tid & 7;    // 0..7  -> cols cg*6..cg*6+5

    // keep the prefetch-overshoot pad zero & deterministic
    if (blockIdx.x == 0) {
        g_expEm[B * S * T + tid] = 0.0f;
        g_expEm[B * S * T + 256 + tid] = 0.0f;
    }

    float acc[4][6];
#pragma unroll
    for (int r = 0; r < 4; r++)
#pragma unroll
        for (int c = 0; c < 6; c++) acc[r][c] = 0.0f;

    for (int kc = 0; kc < H; kc += 64) {
        for (int u = tid; u < 64 * T; u += 256) sh_W[u] = Wm[kc * T + u];

#pragma unroll
        for (int m = 0; m < 8; m++) {
            int u   = tid + m * 256;      // 0..2047
            int row = u >> 4;             // 0..127
            int k4  = u & 15;             // 0..15 (float4 index)
            float4 v = reinterpret_cast<const float4*>(feat)
                        [(size_t)(row0 + row) * (H / 4) + (kc >> 2) + k4];
            sh_feat[(k4 * 4 + 0) * P + row] = v.x;
            sh_feat[(k4 * 4 + 1) * P + row] = v.y;
            sh_feat[(k4 * 4 + 2) * P + row] = v.z;
            sh_feat[(k4 * 4 + 3) * P + row] = v.w;
        }
        __syncthreads();

#pragma unroll 16
        for (int k = 0; k < 64; k++) {
            float f0 = sh_feat[k * P + rg * 4 + 0];
            float f1 = sh_feat[k * P + rg * 4 + 1];
            float f2 = sh_feat[k * P + rg * 4 + 2];
            float f3 = sh_feat[k * P + rg * 4 + 3];
            float2 w01 = *reinterpret_cast<const float2*>(&sh_W[k * T + cg * 6 + 0]);
            float2 w23 = *reinterpret_cast<const float2*>(&sh_W[k * T + cg * 6 + 2]);
            float2 w45 = *reinterpret_cast<const float2*>(&sh_W[k * T + cg * 6 + 4]);
            float w[6] = {w01.x, w01.y, w23.x, w23.y, w45.x, w45.y};
            float f[4] = {f0, f1, f2, f3};
#pragma unroll
            for (int r = 0; r < 4; r++)
#pragma unroll
                for (int c = 0; c < 6; c++)
                    acc[r][c] = fmaf(f[r], w[c], acc[r][c]);
        }
        __syncthreads();
    }

#pragma unroll
    for (int rr = 0; rr < 4; rr++) {
        int row = row0 + rg * 4 + rr;
        int tag = __ldg(&tags[row]);
#pragma unroll
        for (int cc = 0; cc < 6; cc++) {
            int c = cg * 6 + cc;
            float em = acc[rr][cc] + __ldg(&bias[c]);
            g_expEm[(size_t)row * T + c] = expf(em);
            if (c == tag) g_emAtTag[row] = em;
        }
    }
}

// ---------------------------------------------------------------------------
// Kernel B: single-warp forward recursion (warp-synchronous).
// Lane l owns ADJACENT tags j0=2l, j1=2l+1 (lanes 24-31 own padded zero
// slots 48..63). a[j] = exp(alpha[j] - K*ln2);
// step: a'[j] = expEm[j] * dot(a, expT[:,j]).
// Key fix this round: prefetch loads go DIRECTLY into the ring slot and the
// slot is read 4 steps later, so the LDG scoreboard wait is fully deferred
// (~1300 cy slack vs 234-577 cy latency). Pair layout gives 1 LDG.64 + 1
// STS.64 per step instead of 2+2.
// ---------------------------------------------------------------------------

// One step. PH/BUF compile-time; MEASURE at PH==3 only.
#define STEP(sv, PH, BUF, MEASURE) do {                                       \
    float e0 = E[PH].x, e1 = E[PH].y;     /* deferred wait: load from s-4 */  \
    E[PH] = *reinterpret_cast<const float2*>(peBase + (size_t)((sv) + 4) * T);\
    const ulonglong2* av = reinterpret_cast<const ulonglong2*>(a_sh[BUF]);    \
    unsigned long long A0=0ull,A1=0ull,A2=0ull,A3=0ull;                       \
    unsigned long long B0=0ull,B1=0ull,B2=0ull,B3=0ull;                       \
    _Pragma("unroll")                                                         \
    for (int q = 0; q < 12; q += 2) {                                         \
        ulonglong2 u = av[q];                                                 \
        ulonglong2 v = av[q + 1];                                             \
        FMA2(A0, u.x, eT2a[2*q+0]); FMA2(A1, u.y, eT2a[2*q+1]);               \
        FMA2(A2, v.x, eT2a[2*q+2]); FMA2(A3, v.y, eT2a[2*q+3]);               \
        FMA2(B0, u.x, eT2b[2*q+0]); FMA2(B1, u.y, eT2b[2*q+1]);               \
        FMA2(B2, v.x, eT2b[2*q+2]); FMA2(B3, v.y, eT2b[2*q+3]);               \
    }                                                                         \
    unsigned long long tA, tA2, tB, tB2;                                      \
    ADD2(tA, A0, A1); ADD2(tA2, A2, A3); ADD2(tA, tA, tA2);                   \
    ADD2(tB, B0, B1); ADD2(tB2, B2, B3); ADD2(tB, tB, tB2);                   \
    float d0l, d0h, d1l, d1h;                                                 \
    UNPACK2(d0l, d0h, tA); UNPACK2(d1l, d1h, tB);                             \
    float val0 = e0 * (d0l + d0h);                                            \
    float val1 = e1 * (d1l + d1h);                                            \
    if (PH == 0) { val0 *= invM; val1 *= invM; }  /* measures only at PH3 */  \
    *reinterpret_cast<float2*>(&a_sh[(BUF) ^ 1][2 * l]) =                     \
        make_float2(val0, val1);                                              \
    if (MEASURE) {                                                            \
        uint32_t vb = __float_as_uint(fmaxf(val0, val1));                     \
        uint32_t wmax;                                                        \
        asm volatile("redux.sync.max.u32 %0, %1, 0xffffffff;"                 \
                     : "=r"(wmax) : "r"(vb));                                 \
        int k = (int)(wmax >> 23) - 127;      /* M in [2^k, 2^(k+1)) */       \
        invM  = __uint_as_float((uint32_t)(127 - k) << 23);  /* exact 2^-k */ \
        K    += k;                                                            \
        klast = k;                                                            \
    }                                                                         \
    __syncwarp();                                                             \
} while (0)

__global__ __launch_bounds__(32) void fwd_kernel(
    const float* __restrict__ trans,     // [T,T]
    const int*   __restrict__ lengths,   // [B]
    const int*   __restrict__ tags,      // [B,S]
    float*       __restrict__ out)       // [B]
{
    __shared__ float sh_trans[T * T];
    __shared__ __align__(16) float a_sh[2][64];

    const int l  = threadIdx.x;          // lane 0..31
    const int b  = blockIdx.x;
    const int j0 = 2 * l;                // valid tag iff < 48 (l < 24)
    const int j1 = 2 * l + 1;
    const bool act = (l < 24);

    for (int u = l; u < T * T; u += 32) sh_trans[u] = trans[u];
    __syncwarp();

    // transition columns j0 and j1 in registers, packed along 'from' pairs
    unsigned long long eT2a[T / 2], eT2b[T / 2];
    float eStop0 = 0.0f, eStop1 = 0.0f;
    if (act) {
#pragma unroll
        for (int i = 0; i < T / 2; i++) {
            float lo0 = expf(sh_trans[(2 * i + 0) * T + j0]);
            float hi0 = expf(sh_trans[(2 * i + 1) * T + j0]);
            PACK2(eT2a[i], lo0, hi0);
            float lo1 = expf(sh_trans[(2 * i + 0) * T + j1]);
            float hi1 = expf(sh_trans[(2 * i + 1) * T + j1]);
            PACK2(eT2b[i], lo1, hi1);
        }
        eStop0 = expf(sh_trans[j0 * T + STOP_IDX]);
        eStop1 = expf(sh_trans[j1 * T + STOP_IDX]);
    } else {
#pragma unroll
        for (int i = 0; i < T / 2; i++) { eT2a[i] = 0ull; eT2b[i] = 0ull; }
    }

    // START_IDX=46 = 2*23 -> lane 23, x-slot. 47 (odd) is STOP, alpha0=0.
    a_sh[0][2 * l + 0] = (j0 == START_IDX) ? 1.0f : 0.0f;
    a_sh[0][2 * l + 1] = 0.0f;
    __syncwarp();

    const int len = lengths[b];
    const float* peBase = g_expEm + (size_t)b * S * T + 2 * l;  // pair base

    // expEm prefetch ring, depth 4 (float2 per slot; len >= S/2 >= 4)
    float2 E[4];
#pragma unroll
    for (int q = 0; q < 4; q++)
        E[q] = *reinterpret_cast<const float2*>(peBase + (size_t)q * T);

    int   K     = 0;      // total shifted-out exponent (exact)
    int   klast = 0;      // k of most recent measure (tail fixup)
    float invM  = 1.0f;   // pending 2^-k, consumed at next PH0

    int s = 0;
    for (; s + 4 <= len; s += 4) {
        STEP(s + 0, 0, 0, false);
        STEP(s + 1, 1, 1, false);
        STEP(s + 2, 2, 0, false);
        STEP(s + 3, 3, 1, true);
    }
    {
        const int r = len & 3;          // buf is 0 here (4 flips per iter)
        if (r >= 1) STEP(s + 0, 0, 0, false);
        if (r >= 2) STEP(s + 1, 1, 1, false);
        if (r >= 3) STEP(s + 2, 2, 0, false);
    }

    // if the sequence ended on a measure step, its rescale was never applied
    if ((len & 3) == 0) K -= klast;

    // terminal: logZ = K*ln2 + log( sum_j a[j] * exp(trans[j][STOP]) )
    const float* af = a_sh[len & 1];
    float tj = af[2 * l] * eStop0 + af[2 * l + 1] * eStop1;
#pragma unroll
    for (int o = 16; o; o >>= 1) tj += __shfl_xor_sync(0xffffffffu, tj, o);
    const float logZ = (float)K * 0.6931471805599453f + logf(tj);

    // gold score
    const int* btags = tags + b * S;
    float g = 0.0f;
    for (int t = l; t < len; t += 32) {
        int to   = btags[t];
        int from = (t == 0) ? START_IDX : btags[t - 1];
        g += sh_trans[from * T + to] + g_emAtTag[(size_t)b * S + t];
    }
#pragma unroll
    for (int o = 16; o; o >>= 1) g += __shfl_xor_sync(0xffffffffu, g, o);

    if (l == 0) {
        float gold = g + sh_trans[btags[len - 1] * T + STOP_IDX];
        out[b] = logZ - gold;
    }
}

// ---------------------------------------------------------------------------
extern "C" void kernel_launch(void* const* d_in, const int* in_sizes, int n_in,
                              void* d_out, int out_size)
{
    const float* feat    = (const float*)d_in[0];  // lstm_features [B,S,H]
    const float* Wm      = (const float*)d_in[1];  // emission_w [H,T]
    const float* bias    = (const float*)d_in[2];  // emission_b [T]
    const float* trans   = (const float*)d_in[3];  // transitions [T,T]
    const int*   lengths = (const int*)d_in[4];    // [B]
    const int*   tags    = (const int*)d_in[5];    // [B,S]
    float*       out     = (float*)d_out;          // [B]

    emis_kernel<<<(B * S) / 128, 256>>>(feat, Wm, bias, tags);
    fwd_kernel<<<B, 32>>>(trans, lengths, tags, out);
}

// round 13
// speedup vs baseline: 1.2882x; 1.2882x over previous
#include <cuda_runtime.h>
#include <math.h>
#include <stdint.h>

#define B 32
#define S 512
#define H 256
#define T 48
#define START_IDX 46
#define STOP_IDX 47

// Scratch (no allocations allowed). g_expEm padded by 512 floats so the
// unguarded depth-4 prefetch ring may overshoot harmlessly (pad kept zero).
__device__ float g_expEm[B * S * T + 512];   // 3 MB + pad
__device__ float g_emAtTag[B * S];           // 64 KB

#define FMA2(acc, a, b) \
    asm("fma.rn.f32x2 %0, %1, %2, %0;" : "+l"(acc) : "l"(a), "l"(b))
#define ADD2(out, a, b) \
    asm("add.rn.f32x2 %0, %1, %2;" : "=l"(out) : "l"(a), "l"(b))
#define PACK2(out, lo, hi) \
    asm("mov.b64 %0, {%1, %2};" : "=l"(out) : "f"(lo), "f"(hi))
#define UNPACK2(lo, hi, in) \
    asm("mov.b64 {%0, %1}, %2;" : "=f"(lo), "=f"(hi) : "l"(in))

// ---------------------------------------------------------------------------
// Kernel A: emission = feat @ W + bias; store exp(emission) and em[b,s,tags[b,s]]
// Grid: 128 blocks x 256 threads. Each block: 128 rows x 48 cols, K=256.
// ---------------------------------------------------------------------------
__global__ __launch_bounds__(256) void emis_kernel(
    const float* __restrict__ feat,   // [B*S, H]
    const float* __restrict__ Wm,     // [H, T]
    const float* __restrict__ bias,   // [T]
    const int*   __restrict__ tags)   // [B*S]
{
    const int P = 129;                       // smem pitch (conflict break)
    __shared__ float sh_W[64 * T];           // 12 KB
    __shared__ float sh_feat[64 * P];        // 33 KB  (transposed: [k][row])

    const int tid  = threadIdx.x;
    const int row0 = blockIdx.x * 128;
    const int rg   = tid >> 3;   // 0..31 -> rows rg*4..rg*4+3
    const int cg   = tid & 7;    // 0..7  -> cols cg*6..cg*6+5

    // keep the prefetch-overshoot pad zero & deterministic
    if (blockIdx.x == 0) {
        g_expEm[B * S * T + tid] = 0.0f;
        g_expEm[B * S * T + 256 + tid] = 0.0f;
    }

    float acc[4][6];
#pragma unroll
    for (int r = 0; r < 4; r++)
#pragma unroll
        for (int c = 0; c < 6; c++) acc[r][c] = 0.0f;

    for (int kc = 0; kc < H; kc += 64) {
        for (int u = tid; u < 64 * T; u += 256) sh_W[u] = Wm[kc * T + u];

#pragma unroll
        for (int m = 0; m < 8; m++) {
            int u   = tid + m * 256;      // 0..2047
            int row = u >> 4;             // 0..127
            int k4  = u & 15;             // 0..15 (float4 index)
            float4 v = reinterpret_cast<const float4*>(feat)
                        [(size_t)(row0 + row) * (H / 4) + (kc >> 2) + k4];
            sh_feat[(k4 * 4 + 0) * P + row] = v.x;
            sh_feat[(k4 * 4 + 1) * P + row] = v.y;
            sh_feat[(k4 * 4 + 2) * P + row] = v.z;
            sh_feat[(k4 * 4 + 3) * P + row] = v.w;
        }
        __syncthreads();

#pragma unroll 16
        for (int k = 0; k < 64; k++) {
            float f0 = sh_feat[k * P + rg * 4 + 0];
            float f1 = sh_feat[k * P + rg * 4 + 1];
            float f2 = sh_feat[k * P + rg * 4 + 2];
            float f3 = sh_feat[k * P + rg * 4 + 3];
            float2 w01 = *reinterpret_cast<const float2*>(&sh_W[k * T + cg * 6 + 0]);
            float2 w23 = *reinterpret_cast<const float2*>(&sh_W[k * T + cg * 6 + 2]);
            float2 w45 = *reinterpret_cast<const float2*>(&sh_W[k * T + cg * 6 + 4]);
            float w[6] = {w01.x, w01.y, w23.x, w23.y, w45.x, w45.y};
            float f[4] = {f0, f1, f2, f3};
#pragma unroll
            for (int r = 0; r < 4; r++)
#pragma unroll
                for (int c = 0; c < 6; c++)
                    acc[r][c] = fmaf(f[r], w[c], acc[r][c]);
        }
        __syncthreads();
    }

#pragma unroll
    for (int rr = 0; rr < 4; rr++) {
        int row = row0 + rg * 4 + rr;
        int tag = __ldg(&tags[row]);
#pragma unroll
        for (int cc = 0; cc < 6; cc++) {
            int c = cg * 6 + cc;
            float em = acc[rr][cc] + __ldg(&bias[c]);
            g_expEm[(size_t)row * T + c] = expf(em);
            if (c == tag) g_emAtTag[row] = em;
        }
    }
}

// ---------------------------------------------------------------------------
// Kernel B: single-warp forward recursion (warp-synchronous).
// Identical to the 96.4us R8 kernel EXCEPT the expEm prefetch: the ring slot
// is read at step top (waiting on the LDG issued 4 steps (~1300cy) earlier),
// then the new LDG targets the ring register directly with no in-step
// consumer — deferring the scoreboard wait past the L2 latency.
// Lane l owns tags j0=l and j1=l+32 (padded slots stay exactly 0).
// ---------------------------------------------------------------------------

// One recursion step. PH = compile-time phase (0..3), MEASURE at PH==3.
#define STEP(sv, PH, MEASURE) do {                                            \
    float e0 = E0[PH], e1 = E1[PH];   /* deferred wait: load from step s-4 */ \
    E0[PH] = pe0[(size_t)((sv) + 4) * T];   /* unguarded, pad-backed */       \
    E1[PH] = pe1[(size_t)((sv) + 4) * T];                                     \
    const ulonglong2* av = reinterpret_cast<const ulonglong2*>(a_sh[buf]);    \
    unsigned long long A0=0ull,A1=0ull,A2=0ull,A3=0ull;                       \
    unsigned long long B0=0ull,B1=0ull,B2=0ull,B3=0ull;                       \
    _Pragma("unroll")                                                         \
    for (int q = 0; q < 12; q += 2) {                                         \
        ulonglong2 u = av[q];                                                 \
        ulonglong2 v = av[q + 1];                                             \
        FMA2(A0, u.x, eT2a[2*q+0]); FMA2(A1, u.y, eT2a[2*q+1]);               \
        FMA2(A2, v.x, eT2a[2*q+2]); FMA2(A3, v.y, eT2a[2*q+3]);               \
        FMA2(B0, u.x, eT2b[2*q+0]); FMA2(B1, u.y, eT2b[2*q+1]);               \
        FMA2(B2, v.x, eT2b[2*q+2]); FMA2(B3, v.y, eT2b[2*q+3]);               \
    }                                                                         \
    unsigned long long tA, tA2, tB, tB2;                                      \
    ADD2(tA, A0, A1); ADD2(tA2, A2, A3); ADD2(tA, tA, tA2);                   \
    ADD2(tB, B0, B1); ADD2(tB2, B2, B3); ADD2(tB, tB, tB2);                   \
    float d0l, d0h, d1l, d1h;                                                 \
    UNPACK2(d0l, d0h, tA); UNPACK2(d1l, d1h, tB);                             \
    float val0 = e0 * (d0l + d0h) * invM;                                     \
    float val1 = e1 * (d1l + d1h) * invM;                                     \
    invM = 1.0f;                                                              \
    const int nb = buf ^ 1;                                                   \
    a_sh[nb][l]      = val0;                                                  \
    a_sh[nb][l + 32] = val1;                                                  \
    if (MEASURE) {                                                            \
        uint32_t vb = __float_as_uint(fmaxf(val0, val1));                     \
        uint32_t wmax;                                                        \
        asm volatile("redux.sync.max.u32 %0, %1, 0xffffffff;"                 \
                     : "=r"(wmax) : "r"(vb));                                 \
        int k = (int)(wmax >> 23) - 127;      /* M in [2^k, 2^(k+1)) */       \
        invM  = __uint_as_float((uint32_t)(127 - k) << 23);  /* exact 2^-k */ \
        K    += k;                                                            \
        klast = k;                                                            \
    }                                                                         \
    __syncwarp();                                                             \
    buf = nb;                                                                 \
} while (0)

__global__ __launch_bounds__(32) void fwd_kernel(
    const float* __restrict__ trans,     // [T,T]
    const int*   __restrict__ lengths,   // [B]
    const int*   __restrict__ tags,      // [B,S]
    float*       __restrict__ out)       // [B]
{
    __shared__ float sh_trans[T * T];
    __shared__ __align__(16) float a_sh[2][64];

    const int l  = threadIdx.x;          // lane 0..31
    const int b  = blockIdx.x;
    const int j0 = l;                    // always < 48
    const int j1 = l + 32;               // valid tag only if < 48 (l < 16)
    const bool act1 = (j1 < T);

    for (int u = l; u < T * T; u += 32) sh_trans[u] = trans[u];
    __syncwarp();

    // transition columns j0 and j1 in registers, packed along 'from' pairs
    unsigned long long eT2a[T / 2], eT2b[T / 2];
    float eStop0, eStop1 = 0.0f;
#pragma unroll
    for (int i = 0; i < T / 2; i++) {
        float lo = expf(sh_trans[(2 * i + 0) * T + j0]);
        float hi = expf(sh_trans[(2 * i + 1) * T + j0]);
        PACK2(eT2a[i], lo, hi);
    }
    eStop0 = expf(sh_trans[j0 * T + STOP_IDX]);
    if (act1) {
#pragma unroll
        for (int i = 0; i < T / 2; i++) {
            float lo = expf(sh_trans[(2 * i + 0) * T + j1]);
            float hi = expf(sh_trans[(2 * i + 1) * T + j1]);
            PACK2(eT2b[i], lo, hi);
        }
        eStop1 = expf(sh_trans[j1 * T + STOP_IDX]);
    } else {
#pragma unroll
        for (int i = 0; i < T / 2; i++) eT2b[i] = 0ull;
    }

    // START_IDX=46 lives in the UPPER slot (lane 14, j1=46)
    a_sh[0][l]      = (j0 == START_IDX) ? 1.0f : 0.0f;
    a_sh[0][l + 32] = (j1 == START_IDX) ? 1.0f : 0.0f;
    __syncwarp();

    const int len = lengths[b];
    const float* pe0 = g_expEm + (size_t)b * S * T + j0;
    const float* pe1 = g_expEm + (size_t)b * S * T + j1;  // overshoot -> pad/next row

    // expEm prefetch ring, depth 4 (register-resident; len >= S/2 >= 4)
    float E0[4], E1[4];
#pragma unroll
    for (int q = 0; q < 4; q++) {
        E0[q] = pe0[(size_t)q * T];
        E1[q] = pe1[(size_t)q * T];   // garbage for inactive lanes; dot1==0
    }

    int   K     = 0;      // total shifted-out exponent (exact)
    int   klast = 0;      // k of most recent measure (tail fixup)
    int   buf   = 0;
    float invM  = 1.0f;   // pending 2^-k to apply on next step

    int s = 0;
    for (; s + 4 <= len; s += 4) {
        STEP(s + 0, 0, false);
        STEP(s + 1, 1, false);
        STEP(s + 2, 2, false);
        STEP(s + 3, 3, true);
    }
    if (s + 0 < len) STEP(s + 0, 0, false);
    if (s + 1 < len) STEP(s + 1, 1, false);
    if (s + 2 < len) STEP(s + 2, 2, false);

    // if the sequence ended on a measure step, its rescale was never applied
    if ((len & 3) == 0) K -= klast;

    // terminal: logZ = K*ln2 + log( sum_j a[j] * exp(trans[j][STOP]) )
    float tj = a_sh[buf][l] * eStop0 + a_sh[buf][l + 32] * eStop1;
#pragma unroll
    for (int o = 16; o; o >>= 1) tj += __shfl_xor_sync(0xffffffffu, tj, o);
    const float logZ = (float)K * 0.6931471805599453f + logf(tj);

    // gold score
    const int* btags = tags + b * S;
    float g = 0.0f;
    for (int t = l; t < len; t += 32) {
        int to   = btags[t];
        int from = (t == 0) ? START_IDX : btags[t - 1];
        g += sh_trans[from * T + to] + g_emAtTag[(size_t)b * S + t];
    }
#pragma unroll
    for (int o = 16; o; o >>= 1) g += __shfl_xor_sync(0xffffffffu, g, o);

    if (l == 0) {
        float gold = g + sh_trans[btags[len - 1] * T + STOP_IDX];
        out[b] = logZ - gold;
    }
}

// ---------------------------------------------------------------------------
extern "C" void kernel_launch(void* const* d_in, const int* in_sizes, int n_in,
                              void* d_out, int out_size)
{
    const float* feat    = (const float*)d_in[0];  // lstm_features [B,S,H]
    const float* Wm      = (const float*)d_in[1];  // emission_w [H,T]
    const float* bias    = (const float*)d_in[2];  // emission_b [T]
    const float* trans   = (const float*)d_in[3];  // transitions [T,T]
    const int*   lengths = (const int*)d_in[4];    // [B]
    const int*   tags    = (const int*)d_in[5];    // [B,S]
    float*       out     = (float*)d_out;          // [B]

    emis_kernel<<<(B * S) / 128, 256>>>(feat, Wm, bias, tags);
    fwd_kernel<<<B, 32>>>(trans, lengths, tags, out);
}

// round 14
// speedup vs baseline: 1.5714x; 1.2199x over previous
#include <cuda_runtime.h>
#include <math.h>
#include <stdint.h>

#define B 32
#define S 512
#define H 256
#define T 48
#define START_IDX 46
#define STOP_IDX 47

// Scratch (no allocations allowed): exp(emission) and emission-at-gold-tag
__device__ float g_expEm[B * S * T];    // 3 MB
__device__ float g_emAtTag[B * S];      // 64 KB

#define FMA2(acc, a, b) \
    asm("fma.rn.f32x2 %0, %1, %2, %0;" : "+l"(acc) : "l"(a), "l"(b))
#define ADD2(out, a, b) \
    asm("add.rn.f32x2 %0, %1, %2;" : "=l"(out) : "l"(a), "l"(b))
#define PACK2(out, lo, hi) \
    asm("mov.b64 %0, {%1, %2};" : "=l"(out) : "f"(lo), "f"(hi))
#define UNPACK2(lo, hi, in) \
    asm("mov.b64 {%0, %1}, %2;" : "=f"(lo), "=f"(hi) : "l"(in))

// Compiler-only ordering fence: no instruction emitted; stops NVCC from
// reordering the smem stores/loads across the step boundary. HW ordering is
// guaranteed by the in-order per-SM smem pipeline for same-warp accesses.
#define CFENCE() asm volatile("" ::: "memory")

// ---------------------------------------------------------------------------
// Kernel A: emission = feat @ W + bias; store exp(emission) and em[b,s,tags[b,s]]
// Grid: 128 blocks x 256 threads. Each block: 128 rows x 48 cols, K=256.
// ---------------------------------------------------------------------------
__global__ __launch_bounds__(256) void emis_kernel(
    const float* __restrict__ feat,   // [B*S, H]
    const float* __restrict__ Wm,     // [H, T]
    const float* __restrict__ bias,   // [T]
    const int*   __restrict__ tags)   // [B*S]
{
    const int P = 129;                       // smem pitch (conflict break)
    __shared__ float sh_W[64 * T];           // 12 KB
    __shared__ float sh_feat[64 * P];        // 33 KB  (transposed: [k][row])

    const int tid  = threadIdx.x;
    const int row0 = blockIdx.x * 128;
    const int rg   = tid >> 3;   // 0..31 -> rows rg*4..rg*4+3
    const int cg   = tid & 7;    // 0..7  -> cols cg*6..cg*6+5

    float acc[4][6];
#pragma unroll
    for (int r = 0; r < 4; r++)
#pragma unroll
        for (int c = 0; c < 6; c++) acc[r][c] = 0.0f;

    for (int kc = 0; kc < H; kc += 64) {
        for (int u = tid; u < 64 * T; u += 256) sh_W[u] = Wm[kc * T + u];

#pragma unroll
        for (int m = 0; m < 8; m++) {
            int u   = tid + m * 256;      // 0..2047
            int row = u >> 4;             // 0..127
            int k4  = u & 15;             // 0..15 (float4 index)
            float4 v = reinterpret_cast<const float4*>(feat)
                        [(size_t)(row0 + row) * (H / 4) + (kc >> 2) + k4];
            sh_feat[(k4 * 4 + 0) * P + row] = v.x;
            sh_feat[(k4 * 4 + 1) * P + row] = v.y;
            sh_feat[(k4 * 4 + 2) * P + row] = v.z;
            sh_feat[(k4 * 4 + 3) * P + row] = v.w;
        }
        __syncthreads();

#pragma unroll 16
        for (int k = 0; k < 64; k++) {
            float f0 = sh_feat[k * P + rg * 4 + 0];
            float f1 = sh_feat[k * P + rg * 4 + 1];
            float f2 = sh_feat[k * P + rg * 4 + 2];
            float f3 = sh_feat[k * P + rg * 4 + 3];
            float2 w01 = *reinterpret_cast<const float2*>(&sh_W[k * T + cg * 6 + 0]);
            float2 w23 = *reinterpret_cast<const float2*>(&sh_W[k * T + cg * 6 + 2]);
            float2 w45 = *reinterpret_cast<const float2*>(&sh_W[k * T + cg * 6 + 4]);
            float w[6] = {w01.x, w01.y, w23.x, w23.y, w45.x, w45.y};
            float f[4] = {f0, f1, f2, f3};
#pragma unroll
            for (int r = 0; r < 4; r++)
#pragma unroll
                for (int c = 0; c < 6; c++)
                    acc[r][c] = fmaf(f[r], w[c], acc[r][c]);
        }
        __syncthreads();
    }

#pragma unroll
    for (int rr = 0; rr < 4; rr++) {
        int row = row0 + rg * 4 + rr;
        int tag = __ldg(&tags[row]);
#pragma unroll
        for (int cc = 0; cc < 6; cc++) {
            int c = cg * 6 + cc;
            float em = acc[rr][cc] + __ldg(&bias[c]);
            g_expEm[(size_t)row * T + c] = expf(em);
            if (c == tag) g_emAtTag[row] = em;
        }
    }
}

// ---------------------------------------------------------------------------
// Kernel B: single-warp forward recursion (warp-synchronous).
// Byte-identical to the 96.4us R8 kernel EXCEPT: the per-step __syncwarp()
// is replaced by a compiler-only fence. The loop is fully convergent
// (uniform branches), same-warp STS->LDS order is preserved by the in-order
// smem pipeline, and redux.sync every 4th step bounds any lane drift.
// Lane l owns tags j0=l and j1=l+32 (padded slots stay exactly 0).
// ---------------------------------------------------------------------------

// One recursion step. PH = compile-time phase (0..3), MEASURE at PH==3.
#define STEP(sv, PH, MEASURE) do {                                            \
    const ulonglong2* av = reinterpret_cast<const ulonglong2*>(a_sh[buf]);    \
    unsigned long long A0=0ull,A1=0ull,A2=0ull,A3=0ull;                       \
    unsigned long long B0=0ull,B1=0ull,B2=0ull,B3=0ull;                       \
    _Pragma("unroll")                                                         \
    for (int q = 0; q < 12; q += 2) {                                         \
        ulonglong2 u = av[q];                                                 \
        ulonglong2 v = av[q + 1];                                             \
        FMA2(A0, u.x, eT2a[2*q+0]); FMA2(A1, u.y, eT2a[2*q+1]);               \
        FMA2(A2, v.x, eT2a[2*q+2]); FMA2(A3, v.y, eT2a[2*q+3]);               \
        FMA2(B0, u.x, eT2b[2*q+0]); FMA2(B1, u.y, eT2b[2*q+1]);               \
        FMA2(B2, v.x, eT2b[2*q+2]); FMA2(B3, v.y, eT2b[2*q+3]);               \
    }                                                                         \
    unsigned long long tA, tA2, tB, tB2;                                      \
    ADD2(tA, A0, A1); ADD2(tA2, A2, A3); ADD2(tA, tA, tA2);                   \
    ADD2(tB, B0, B1); ADD2(tB2, B2, B3); ADD2(tB, tB, tB2);                   \
    float d0l, d0h, d1l, d1h;                                                 \
    UNPACK2(d0l, d0h, tA); UNPACK2(d1l, d1h, tB);                             \
    float val0 = E0[PH] * (d0l + d0h) * invM;                                 \
    float val1 = E1[PH] * (d1l + d1h) * invM;                                 \
    invM = 1.0f;                                                              \
    {                                                                         \
        int sp = (sv) + 4;                                                    \
        E0[PH] = (sp < len) ? pe0[(size_t)sp * T] : 0.0f;                     \
        E1[PH] = (act1 && sp < len) ? pe1[(size_t)sp * T] : 0.0f;             \
    }                                                                         \
    const int nb = buf ^ 1;                                                   \
    a_sh[nb][l]      = val0;                                                  \
    a_sh[nb][l + 32] = val1;                                                  \
    if (MEASURE) {                                                            \
        uint32_t vb = __float_as_uint(fmaxf(val0, val1));                     \
        uint32_t wmax;                                                        \
        asm volatile("redux.sync.max.u32 %0, %1, 0xffffffff;"                 \
                     : "=r"(wmax) : "r"(vb));                                 \
        int k = (int)(wmax >> 23) - 127;      /* M in [2^k, 2^(k+1)) */       \
        invM  = __uint_as_float((uint32_t)(127 - k) << 23);  /* exact 2^-k */ \
        K    += k;                                                            \
        klast = k;                                                            \
    }                                                                         \
    CFENCE();                                                                 \
    buf = nb;                                                                 \
} while (0)

__global__ __launch_bounds__(32) void fwd_kernel(
    const float* __restrict__ trans,     // [T,T]
    const int*   __restrict__ lengths,   // [B]
    const int*   __restrict__ tags,      // [B,S]
    float*       __restrict__ out)       // [B]
{
    __shared__ float sh_trans[T * T];
    __shared__ __align__(16) float a_sh[2][64];

    const int l  = threadIdx.x;          // lane 0..31
    const int b  = blockIdx.x;
    const int j0 = l;                    // always < 48
    const int j1 = l + 32;               // valid tag only if < 48 (l < 16)
    const bool act1 = (j1 < T);

    for (int u = l; u < T * T; u += 32) sh_trans[u] = trans[u];
    __syncwarp();

    // transition columns j0 and j1 in registers, packed along 'from' pairs
    unsigned long long eT2a[T / 2], eT2b[T / 2];
    float eStop0, eStop1 = 0.0f;
#pragma unroll
    for (int i = 0; i < T / 2; i++) {
        float lo = expf(sh_trans[(2 * i + 0) * T + j0]);
        float hi = expf(sh_trans[(2 * i + 1) * T + j0]);
        PACK2(eT2a[i], lo, hi);
    }
    eStop0 = expf(sh_trans[j0 * T + STOP_IDX]);
    if (act1) {
#pragma unroll
        for (int i = 0; i < T / 2; i++) {
            float lo = expf(sh_trans[(2 * i + 0) * T + j1]);
            float hi = expf(sh_trans[(2 * i + 1) * T + j1]);
            PACK2(eT2b[i], lo, hi);
        }
        eStop1 = expf(sh_trans[j1 * T + STOP_IDX]);
    } else {
#pragma unroll
        for (int i = 0; i < T / 2; i++) eT2b[i] = 0ull;
    }

    // START_IDX=46 lives in the UPPER slot (lane 14, j1=46)
    a_sh[0][l]      = (j0 == START_IDX) ? 1.0f : 0.0f;
    a_sh[0][l + 32] = (j1 == START_IDX) ? 1.0f : 0.0f;
    __syncwarp();

    const int len = lengths[b];
    const float* pe0 = g_expEm + (size_t)b * S * T + j0;
    const float* pe1 = g_expEm + (size_t)b * S * T + j1;

    // expEm prefetch ring, depth 4 (register-resident; len >= S/2 >= 4)
    float E0[4], E1[4];
#pragma unroll
    for (int q = 0; q < 4; q++) {
        E0[q] = pe0[(size_t)q * T];
        E1[q] = pe1[(size_t)q * T];   // garbage for inactive lanes; dot1==0
    }

    int   K     = 0;      // total shifted-out exponent (exact)
    int   klast = 0;      // k of most recent measure (tail fixup)
    int   buf   = 0;
    float invM  = 1.0f;   // pending 2^-k to apply on next step

    int s = 0;
    for (; s + 4 <= len; s += 4) {
        STEP(s + 0, 0, false);
        STEP(s + 1, 1, false);
        STEP(s + 2, 2, false);
        STEP(s + 3, 3, true);
    }
    if (s + 0 < len) STEP(s + 0, 0, false);
    if (s + 1 < len) STEP(s + 1, 1, false);
    if (s + 2 < len) STEP(s + 2, 2, false);

    // if the sequence ended on a measure step, its rescale was never applied
    if ((len & 3) == 0) K -= klast;

    __syncwarp();   // real sync before terminal cross-lane reads

    // terminal: logZ = K*ln2 + log( sum_j a[j] * exp(trans[j][STOP]) )
    float tj = a_sh[buf][l] * eStop0 + a_sh[buf][l + 32] * eStop1;
#pragma unroll
    for (int o = 16; o; o >>= 1) tj += __shfl_xor_sync(0xffffffffu, tj, o);
    const float logZ = (float)K * 0.6931471805599453f + logf(tj);

    // gold score
    const int* btags = tags + b * S;
    float g = 0.0f;
    for (int t = l; t < len; t += 32) {
        int to   = btags[t];
        int from = (t == 0) ? START_IDX : btags[t - 1];
        g += sh_trans[from * T + to] + g_emAtTag[(size_t)b * S + t];
    }
#pragma unroll
    for (int o = 16; o; o >>= 1) g += __shfl_xor_sync(0xffffffffu, g, o);

    if (l == 0) {
        float gold = g + sh_trans[btags[len - 1] * T + STOP_IDX];
        out[b] = logZ - gold;
    }
}

// ---------------------------------------------------------------------------
extern "C" void kernel_launch(void* const* d_in, const int* in_sizes, int n_in,
                              void* d_out, int out_size)
{
    const float* feat    = (const float*)d_in[0];  // lstm_features [B,S,H]
    const float* Wm      = (const float*)d_in[1];  // emission_w [H,T]
    const float* bias    = (const float*)d_in[2];  // emission_b [T]
    const float* trans   = (const float*)d_in[3];  // transitions [T,T]
    const int*   lengths = (const int*)d_in[4];    // [B]
    const int*   tags    = (const int*)d_in[5];    // [B,S]
    float*       out     = (float*)d_out;          // [B]

    emis_kernel<<<(B * S) / 128, 256>>>(feat, Wm, bias, tags);
    fwd_kernel<<<B, 32>>>(trans, lengths, tags, out);
}